// round 7
// baseline (speedup 1.0000x reference)
#include <cuda_runtime.h>
#include <cuda_bf16.h>

// ---------------------------------------------------------------------------
// ModelSimple: conv4d(1->5,k7)+ReLU -> conv4d(5->10,k7)+ReLU -> Linear -> sigmoid
// R7: R6 (GMEM pre-duplicated weight pairs, broadcast LDS.64, contiguous f4
//     staging) with the 16B-alignment bug fixed: __align__(16) arrays and
//     even per-slot stride (12006) so every float4 staging load is aligned.
// ---------------------------------------------------------------------------

#define ULL unsigned long long

__device__ __forceinline__ ULL pack2(float a, float b) {
    ULL r;
    asm("mov.b64 %0, {%1, %2};" : "=l"(r) : "f"(a), "f"(b));
    return r;
}
__device__ __forceinline__ ULL fma2(ULL a, ULL b, ULL c) {
    ULL d;
    asm("fma.rn.f32x2 %0, %1, %2, %3;" : "=l"(d) : "l"(a), "l"(b), "l"(c));
    return d;
}
__device__ __forceinline__ ULL add2(ULL a, ULL b) {
    ULL d;
    asm("add.rn.f32x2 %0, %1, %2;" : "=l"(d) : "l"(a), "l"(b));
    return d;
}
__device__ __forceinline__ float2 unpack2(ULL v) {
    float2 f;
    asm("mov.b64 {%0, %1}, %2;" : "=f"(f.x), "=f"(f.y) : "l"(v));
    return f;
}

// Scratch (device globals: allocation-free per harness rules)
__device__ float g_h1[128 * 5 * 20736];   // [b][oc][oh*1728 + ow*144 + od*12 + ot]
__device__ float g_h2[128 * 10 * 1296];   // [b][oc][oh*216 + ow*36 + od*6 + ot]
__device__ __align__(16) ULL g_w1d[12006];         // w1 dup pairs [oc][ki][kt], 1 pad
__device__ __align__(16) ULL g_w2d[10 * 12006];    // w2 dup pairs per slot(ocg*5+ic)

// ---------------------------------------------------------------------------
// Weight duplication prep kernels (trivial cost, graph-capturable)
// ---------------------------------------------------------------------------
__global__ void dup_w1_kernel(const float* __restrict__ w1) {
    const int i = blockIdx.x * 256 + threadIdx.x;
    if (i < 12006) {
        const float v = (i < 12005) ? w1[i] : 0.0f;
        g_w1d[i] = pack2(v, v);
    }
}
__global__ void dup_w2_kernel(const float* __restrict__ w2) {
    const int i = blockIdx.x * 256 + threadIdx.x;
    if (i < 10 * 12006) {
        const int slot = i / 12006;           // slot = ocg*5 + ic
        const int j    = i - slot * 12006;    // [ocl][2401], last is pad
        const int ocg  = slot / 5;
        const int ic   = slot - ocg * 5;
        float v = 0.0f;
        if (j < 12005) {
            const int ocl = j / 2401;
            const int r   = j - ocl * 2401;
            v = w2[(size_t)((ocg * 5 + ocl) * 5 + ic) * 2401 + r];
        }
        g_w2d[i] = pack2(v, v);
    }
}

// ---------------------------------------------------------------------------
// conv1: grid = 128*12*2 (b, oh, ow-half); 864 thr = 6 khw-groups x 144
// (ow6, od12, ot2). SMEM: x slab [7,12,18,18]=27216 f (108,864B) +
// dup w1 12006 ULL (96,048B) = 204,912 B. Reduction reuses slab region.
// ---------------------------------------------------------------------------
__global__ __launch_bounds__(864, 1)
void conv1_kernel(const float* __restrict__ x,
                  const float* __restrict__ b1) {
    extern __shared__ float sm[];
    float* sx  = sm;                         // 27216 floats (dead after compute)
    ULL*   swU = (ULL*)(sm + 27216);         // 12006 ULL dup pairs (16B aligned)

    const int bx  = blockIdx.x;
    const int b   = bx / 24;
    const int oh  = (bx % 24) >> 1;
    const int owb = (bx & 1) * 6;
    const int tid = threadIdx.x;

    // Stage x slab (per kh: 972 contiguous float4) + contiguous weight copy
    {
        const float* src = x + (size_t)b * 104976 + oh * 5832 + owb * 324;
        float4* d4 = (float4*)sx;
        for (int i = tid; i < 6804; i += 864) {
            const int kh = i / 972;
            const int j  = i - kh * 972;
            d4[i] = ((const float4*)(src + kh * 5832))[j];
        }
        const float4* ws = (const float4*)g_w1d;   // 12006 ULL = 6003 f4
        float4* wd = (float4*)swU;
        for (int i = tid; i < 6003; i += 864) wd[i] = ws[i];
    }
    __syncthreads();

    const int g   = tid / 144;           // khw group 0..5 (9/8/8/8/8/8)
    const int t   = tid - g * 144;
    const int ow  = t / 24;              // 0..5 local
    const int r   = t % 24;
    const int od  = r >> 1;
    const int ot0 = (r & 1) * 6;

    ULL acc[5][3];
    #pragma unroll
    for (int oc = 0; oc < 5; oc++)
        #pragma unroll
        for (int p = 0; p < 3; p++) acc[oc][p] = 0ULL;

    const int colbase = od * 18 + ot0;
    const int k0 = (g == 0) ? 0 : (9 + (g - 1) * 8);
    const int k1 = k0 + ((g == 0) ? 9 : 8);

    #pragma unroll 1
    for (int khw = k0; khw < k1; khw++) {
        const int kh = khw / 7;
        const int kw = khw - kh * 7;
        const float* rowc = sx + kh * 3888 + (ow + kw) * 324 + colbase;
        #pragma unroll 1
        for (int kd = 0; kd < 7; kd++) {
            const float* row = rowc + kd * 18;
            float2 v0 = *(const float2*)(row + 0);
            float2 v1 = *(const float2*)(row + 2);
            float2 v2 = *(const float2*)(row + 4);
            float2 v3 = *(const float2*)(row + 6);
            float2 v4 = *(const float2*)(row + 8);
            float2 v5 = *(const float2*)(row + 10);
            ULL xp[11];
            xp[0]  = pack2(v0.x, v0.y);
            xp[2]  = pack2(v1.x, v1.y);
            xp[4]  = pack2(v2.x, v2.y);
            xp[6]  = pack2(v3.x, v3.y);
            xp[8]  = pack2(v4.x, v4.y);
            xp[10] = pack2(v5.x, v5.y);
            xp[1]  = pack2(v0.y, v1.x);
            xp[3]  = pack2(v1.y, v2.x);
            xp[5]  = pack2(v2.y, v3.x);
            xp[7]  = pack2(v3.y, v4.x);
            xp[9]  = pack2(v4.y, v5.x);

            const int kib = (khw * 7 + kd) * 7;
            #pragma unroll
            for (int oc = 0; oc < 5; oc++) {
                const ULL* wq = swU + oc * 2401 + kib;
                const ULL w0 = wq[0], w1_ = wq[1], w2_ = wq[2], w3_ = wq[3];
                const ULL w4 = wq[4], w5 = wq[5], w6 = wq[6];
                acc[oc][0] = fma2(xp[0], w0, acc[oc][0]);
                acc[oc][1] = fma2(xp[2], w0, acc[oc][1]);
                acc[oc][2] = fma2(xp[4], w0, acc[oc][2]);
                acc[oc][0] = fma2(xp[1], w1_, acc[oc][0]);
                acc[oc][1] = fma2(xp[3], w1_, acc[oc][1]);
                acc[oc][2] = fma2(xp[5], w1_, acc[oc][2]);
                acc[oc][0] = fma2(xp[2], w2_, acc[oc][0]);
                acc[oc][1] = fma2(xp[4], w2_, acc[oc][1]);
                acc[oc][2] = fma2(xp[6], w2_, acc[oc][2]);
                acc[oc][0] = fma2(xp[3], w3_, acc[oc][0]);
                acc[oc][1] = fma2(xp[5], w3_, acc[oc][1]);
                acc[oc][2] = fma2(xp[7], w3_, acc[oc][2]);
                acc[oc][0] = fma2(xp[4], w4, acc[oc][0]);
                acc[oc][1] = fma2(xp[6], w4, acc[oc][1]);
                acc[oc][2] = fma2(xp[8], w4, acc[oc][2]);
                acc[oc][0] = fma2(xp[5], w5, acc[oc][0]);
                acc[oc][1] = fma2(xp[7], w5, acc[oc][1]);
                acc[oc][2] = fma2(xp[9], w5, acc[oc][2]);
                acc[oc][0] = fma2(xp[6], w6, acc[oc][0]);
                acc[oc][1] = fma2(xp[8], w6, acc[oc][1]);
                acc[oc][2] = fma2(xp[10], w6, acc[oc][2]);
            }
        }
    }

    // 6-way khw reduction through SMEM (5*144*15 ULL = 86,400B into slab region)
    __syncthreads();
    ULL* red = (ULL*)sm;
    if (g != 0) {
        #pragma unroll
        for (int oc = 0; oc < 5; oc++)
            #pragma unroll
            for (int p = 0; p < 3; p++)
                red[((g - 1) * 144 + t) * 15 + oc * 3 + p] = acc[oc][p];
    }
    __syncthreads();

    if (g == 0) {
        const int sbase = oh * 1728 + (owb + ow) * 144 + od * 12 + ot0;
        #pragma unroll
        for (int oc = 0; oc < 5; oc++) {
            const float bb = __ldg(b1 + oc);
            float* dst = g_h1 + (size_t)(b * 5 + oc) * 20736 + sbase;
            #pragma unroll
            for (int p = 0; p < 3; p++) {
                ULL a = acc[oc][p];
                #pragma unroll
                for (int q = 0; q < 5; q++)
                    a = add2(a, red[(q * 144 + t) * 15 + oc * 3 + p]);
                const float2 f = unpack2(a);
                float2 o;
                o.x = fmaxf(f.x + bb, 0.0f);
                o.y = fmaxf(f.y + bb, 0.0f);
                *(float2*)(dst + 2 * p) = o;
            }
        }
    }
}

// ---------------------------------------------------------------------------
// conv2: grid = 128*2 (b, oc-group of 5); 864 thr = 4 khw-groups x 216
// Loop ic: SMEM h1 slab 20736 f (82,944B) + dup w 12006 ULL (96,048B) = 178,992B
// ---------------------------------------------------------------------------
__global__ __launch_bounds__(864, 1)
void conv2_kernel(const float* __restrict__ b2) {
    extern __shared__ float sm[];
    float* sx  = sm;                         // 20736 floats
    ULL*   swU = (ULL*)(sm + 20736);         // 12006 ULL (16B aligned)

    const int bx  = blockIdx.x;
    const int b   = bx >> 1;
    const int ocg = bx & 1;
    const int ocb = ocg * 5;
    const int tid = threadIdx.x;
    const int g   = tid / 216;               // khw group 0..3 (13/12/12/12)
    const int t   = tid - g * 216;
    const int oh  = t / 36;
    const int ow  = (t % 36) / 6;
    const int od  = t % 6;

    ULL acc[5][3];
    #pragma unroll
    for (int oc = 0; oc < 5; oc++)
        #pragma unroll
        for (int p = 0; p < 3; p++) acc[oc][p] = 0ULL;

    const int k0 = (g == 0) ? 0 : (13 + (g - 1) * 12);
    const int k1 = k0 + ((g == 0) ? 13 : 12);

    for (int ic = 0; ic < 5; ic++) {
        __syncthreads();   // protect previous iteration's SMEM reads
        {
            const float4* s4 = (const float4*)(g_h1 + (size_t)(b * 5 + ic) * 20736);
            float4* d4 = (float4*)sx;
            for (int i = tid; i < 5184; i += 864) d4[i] = s4[i];
            const float4* ws = (const float4*)(g_w2d + (size_t)(ocg * 5 + ic) * 12006);
            float4* wd = (float4*)swU;
            for (int i = tid; i < 6003; i += 864) wd[i] = ws[i];
        }
        __syncthreads();

        #pragma unroll 1
        for (int khw = k0; khw < k1; khw++) {
            const int kh = khw / 7;
            const int kw = khw - kh * 7;
            const float* rowc = sx + ((oh + kh) * 12 + ow + kw) * 144 + od * 12;
            #pragma unroll 1
            for (int kd = 0; kd < 7; kd++) {
                const float* row = rowc + kd * 12;
                float2 v0 = *(const float2*)(row + 0);
                float2 v1 = *(const float2*)(row + 2);
                float2 v2 = *(const float2*)(row + 4);
                float2 v3 = *(const float2*)(row + 6);
                float2 v4 = *(const float2*)(row + 8);
                float2 v5 = *(const float2*)(row + 10);
                ULL xp[11];
                xp[0]  = pack2(v0.x, v0.y);
                xp[2]  = pack2(v1.x, v1.y);
                xp[4]  = pack2(v2.x, v2.y);
                xp[6]  = pack2(v3.x, v3.y);
                xp[8]  = pack2(v4.x, v4.y);
                xp[10] = pack2(v5.x, v5.y);
                xp[1]  = pack2(v0.y, v1.x);
                xp[3]  = pack2(v1.y, v2.x);
                xp[5]  = pack2(v2.y, v3.x);
                xp[7]  = pack2(v3.y, v4.x);
                xp[9]  = pack2(v4.y, v5.x);

                const int kib = (khw * 7 + kd) * 7;
                #pragma unroll
                for (int oc = 0; oc < 5; oc++) {
                    const ULL* wq = swU + oc * 2401 + kib;
                    const ULL w0 = wq[0], w1_ = wq[1], w2_ = wq[2], w3_ = wq[3];
                    const ULL w4 = wq[4], w5 = wq[5], w6 = wq[6];
                    acc[oc][0] = fma2(xp[0], w0, acc[oc][0]);
                    acc[oc][1] = fma2(xp[2], w0, acc[oc][1]);
                    acc[oc][2] = fma2(xp[4], w0, acc[oc][2]);
                    acc[oc][0] = fma2(xp[1], w1_, acc[oc][0]);
                    acc[oc][1] = fma2(xp[3], w1_, acc[oc][1]);
                    acc[oc][2] = fma2(xp[5], w1_, acc[oc][2]);
                    acc[oc][0] = fma2(xp[2], w2_, acc[oc][0]);
                    acc[oc][1] = fma2(xp[4], w2_, acc[oc][1]);
                    acc[oc][2] = fma2(xp[6], w2_, acc[oc][2]);
                    acc[oc][0] = fma2(xp[3], w3_, acc[oc][0]);
                    acc[oc][1] = fma2(xp[5], w3_, acc[oc][1]);
                    acc[oc][2] = fma2(xp[7], w3_, acc[oc][2]);
                    acc[oc][0] = fma2(xp[4], w4, acc[oc][0]);
                    acc[oc][1] = fma2(xp[6], w4, acc[oc][1]);
                    acc[oc][2] = fma2(xp[8], w4, acc[oc][2]);
                    acc[oc][0] = fma2(xp[5], w5, acc[oc][0]);
                    acc[oc][1] = fma2(xp[7], w5, acc[oc][1]);
                    acc[oc][2] = fma2(xp[9], w5, acc[oc][2]);
                    acc[oc][0] = fma2(xp[6], w6, acc[oc][0]);
                    acc[oc][1] = fma2(xp[8], w6, acc[oc][1]);
                    acc[oc][2] = fma2(xp[10], w6, acc[oc][2]);
                }
            }
        }
    }

    // 4-way khw reduction through SMEM (3*216*15 ULL = 77,760B into slab region)
    __syncthreads();
    ULL* red = (ULL*)sm;
    if (g != 0) {
        #pragma unroll
        for (int oc = 0; oc < 5; oc++)
            #pragma unroll
            for (int p = 0; p < 3; p++)
                red[((g - 1) * 216 + t) * 15 + oc * 3 + p] = acc[oc][p];
    }
    __syncthreads();

    if (g == 0) {
        const int sp = oh * 216 + ow * 36 + od * 6;
        #pragma unroll
        for (int oc = 0; oc < 5; oc++) {
            const float bb = __ldg(b2 + ocb + oc);
            float* dst = g_h2 + (size_t)(b * 10 + ocb + oc) * 1296 + sp;
            #pragma unroll
            for (int p = 0; p < 3; p++) {
                ULL a = acc[oc][p];
                #pragma unroll
                for (int q = 0; q < 3; q++)
                    a = add2(a, red[(q * 216 + t) * 15 + oc * 3 + p]);
                const float2 f = unpack2(a);
                float2 o;
                o.x = fmaxf(f.x + bb, 0.0f);
                o.y = fmaxf(f.y + bb, 0.0f);
                *(float2*)(dst + 2 * p) = o;
            }
        }
    }
}

// ---------------------------------------------------------------------------
// head: Linear(12960 -> 1) + sigmoid. grid = 128 (b), 128 threads.
// ---------------------------------------------------------------------------
__global__ __launch_bounds__(128, 8)
void head_kernel(const float* __restrict__ wl,
                 const float* __restrict__ bl,
                 float* __restrict__ out) {
    const int b   = blockIdx.x;
    const int tid = threadIdx.x;
    const float* h = g_h2 + (size_t)b * 12960;

    float sum = 0.0f;
    for (int i = tid; i < 12960; i += 128)
        sum += h[i] * wl[i];

    #pragma unroll
    for (int o = 16; o > 0; o >>= 1)
        sum += __shfl_xor_sync(0xffffffffu, sum, o);

    __shared__ float red[4];
    if ((tid & 31) == 0) red[tid >> 5] = sum;
    __syncthreads();
    if (tid == 0) {
        float z = red[0] + red[1] + red[2] + red[3] + bl[0];
        out[b] = 1.0f / (1.0f + expf(-z));
    }
}

// ---------------------------------------------------------------------------
extern "C" void kernel_launch(void* const* d_in, const int* in_sizes, int n_in,
                              void* d_out, int out_size) {
    const float* x  = (const float*)d_in[0];
    const float* w1 = (const float*)d_in[1];
    const float* b1 = (const float*)d_in[2];
    const float* w2 = (const float*)d_in[3];
    const float* b2 = (const float*)d_in[4];
    const float* wl = (const float*)d_in[5];
    const float* bl = (const float*)d_in[6];

    const int smem1 = 108864 + 96048;  // 204,912 B
    const int smem2 = 82944 + 96048;   // 178,992 B
    cudaFuncSetAttribute(conv1_kernel, cudaFuncAttributeMaxDynamicSharedMemorySize, smem1);
    cudaFuncSetAttribute(conv2_kernel, cudaFuncAttributeMaxDynamicSharedMemorySize, smem2);

    dup_w1_kernel<<<(12006 + 255) / 256, 256>>>(w1);
    dup_w2_kernel<<<(10 * 12006 + 255) / 256, 256>>>(w2);
    conv1_kernel<<<128 * 24, 864, smem1>>>(x, b1);
    conv2_kernel<<<128 * 2, 864, smem2>>>(b2);
    head_kernel<<<128, 128>>>(wl, bl, (float*)d_out);
}